// round 2
// baseline (speedup 1.0000x reference)
#include <cuda_runtime.h>
#include <cuda_bf16.h>

#define NATOMS 256
#define NMOL   4
#define NPAIRS 8192
#define KEC      14.3996f
#define AA       0.3f
#define PI_F     3.14159265358979323846f
#define SQRTPI_F 1.7724538509055160273f
#define TWOPI_F  6.2831853071795864769f
#define INV2A      (1.0f/(2.0f*AA))
#define TWOA_SQPI  (2.0f*AA/SQRTPI_F)
#define FOURA_SQPI (4.0f*AA/SQRTPI_F)
#define INV_A_SQPI (1.0f/(AA*SQRTPI_F))

__device__ float  g_Rs[NATOMS][3];
__device__ float  g_Hc[6][NATOMS*NATOMS];
__device__ float  g_Gc[NATOMS][3];
__device__ double g_Ec;
__device__ double g_Eb[NMOL];
__device__ float  g_Gb[NATOMS][3];
__device__ float  g_Hb[6][NPAIRS];
__device__ float  g_v[NATOMS][3];
__device__ float  g_wc[NATOMS][3];
__device__ float  g_wb[NATOMS][3];
__device__ float  g_ff[NMOL][3];

__device__ __forceinline__ float blockReduce256(float v, float* sh) {
    const unsigned full = 0xffffffffu;
    #pragma unroll
    for (int o = 16; o > 0; o >>= 1) v += __shfl_down_sync(full, v, o);
    int lane = threadIdx.x & 31, w = threadIdx.x >> 5;
    if (lane == 0) sh[w] = v;
    __syncthreads();
    float r = 0.f;
    if (w == 0) {
        r = (lane < (int)(blockDim.x >> 5)) ? sh[lane] : 0.f;
        #pragma unroll
        for (int o = 4; o > 0; o >>= 1) r += __shfl_down_sync(full, r, o);
    }
    __syncthreads();
    return r;
}

// F(z)=(e1+e2)/d ; F'=e1-e2 ; F''=d(e1+e2)-(4a/sqrt(pi))*exp(-u^2-(az)^2)
__device__ __forceinline__ void Ffuncs(float d2, float z, float& F, float& Fz, float& Fzz) {
    float d  = sqrtf(d2);
    float u  = d * INV2A;
    float az = AA * z;
    float dz = d * z;
    float e1 = __expf(dz)  * erfcf(u + az);
    float e2 = __expf(-dz) * erfcf(u - az);
    float s  = e1 + e2;
    F   = __fdividef(s, d);
    Fz  = e1 - e2;
    Fzz = d * s - FOURA_SQPI * __expf(-(u * u + az * az));
}

__global__ void k_prep(const float* __restrict__ R, const float* __restrict__ shift,
                       const int* __restrict__ idx_m, const int* __restrict__ is_film) {
    int a = threadIdx.x;
    int m = idx_m[a];
    float f = (is_film[a] > 0) ? 1.f : 0.f;
    #pragma unroll
    for (int c = 0; c < 3; c++) {
        g_Rs[a][c] = R[a * 3 + c] + f * shift[m * 3 + c];
        g_Gb[a][c] = 0.f;
        g_wb[a][c] = 0.f;
    }
    if (a == 0) g_Ec = 0.0;
    if (a < NMOL) g_Eb[a] = 0.0;
}

__global__ void __launch_bounds__(256) k_coulomb(const float* __restrict__ q,
                                                 const float* __restrict__ cell,
                                                 const float* __restrict__ recip) {
    int i = blockIdx.x, j = threadIdx.x;
    float dx = g_Rs[i][0] - g_Rs[j][0];
    float dy = g_Rs[i][1] - g_Rs[j][1];
    float dz = g_Rs[i][2] - g_Rs[j][2];
    float qq = q[i] * q[j];

    float c0x = cell[0], c0y = cell[1], c0z = cell[2];
    float c1x = cell[3], c1y = cell[4], c1z = cell[5];
    float crx = c0y * c1z - c0z * c1y;
    float cry = c0z * c1x - c0x * c1z;
    float crz = c0x * c1y - c0y * c1x;
    float area = sqrtf(crx * crx + cry * cry + crz * crz);
    float K0x = TWOPI_F * recip[0], K0y = TWOPI_F * recip[1], K0z = TWOPI_F * recip[2];
    float K1x = TWOPI_F * recip[3], K1y = TWOPI_F * recip[4], K1z = TWOPI_F * recip[5];

    float Ek = 0.f, Gkx = 0.f, Gky = 0.f, Gkz = 0.f;
    float Kxx = 0.f, Kyy = 0.f, Kzz = 0.f, Kxy = 0.f, Kxz = 0.f, Kyz = 0.f;

    float alpha = K0x * dx + K0y * dy + K0z * dz;
    float beta  = K1x * dx + K1y * dy + K1z * dz;
    float sa, ca, sb, cb;
    sincosf(alpha, &sa, &ca);
    sincosf(beta,  &sb, &cb);

    auto accum = [&](float cT, float sT, float hx, float hy, float hz,
                     float F, float Fz, float Fzz) {
        float cF  = cT * F;
        float sF  = sT * F;
        float sFz = sT * Fz;
        Ek  += cF;
        Gkx -= sF * hx;
        Gky -= sF * hy;
        Gkz += cT * Fz - sF * hz;
        Kxx -= cF * hx * hx;
        Kyy -= cF * hy * hy;
        Kxy -= cF * hx * hy;
        Kxz -= cF * hx * hz + sFz * hx;
        Kyz -= cF * hy * hz + sFz * hy;
        Kzz += cT * Fzz - cF * hz * hz - 2.f * sFz * hz;
    };

    float cA = 1.f, sA = 0.f;
    #pragma unroll 1
    for (int k0 = 0; k0 <= 6; k0++) {
        float fk0 = (float)k0;
        float h0x = fk0 * K0x, h0y = fk0 * K0y, h0z = fk0 * K0z;
        float cB, sB;
        int j1s;
        if (k0 == 0) { j1s = 1; cB = cb; sB = sb; }
        else         { j1s = 0; cB = 1.f; sB = 0.f; }
        #pragma unroll 1
        for (int j1 = j1s; j1 <= 6; j1++) {
            if (j1 == 0) {
                float d2 = h0x * h0x + h0y * h0y + h0z * h0z;
                float F, Fz, Fzz; Ffuncs(d2, dz, F, Fz, Fzz);
                accum(cA, sA, h0x, h0y, h0z, F, Fz, Fzz);
            } else {
                float fj = (float)j1;
                float hpx = h0x + fj * K1x, hpy = h0y + fj * K1y, hpz = h0z + fj * K1z;
                float d2p = hpx * hpx + hpy * hpy + hpz * hpz;
                float F, Fz, Fzz; Ffuncs(d2p, dz, F, Fz, Fzz);
                float cP = cA * cB - sA * sB, sP = sA * cB + cA * sB;
                accum(cP, sP, hpx, hpy, hpz, F, Fz, Fzz);
                if (k0 > 0) {
                    float hmx = h0x - fj * K1x, hmy = h0y - fj * K1y, hmz = h0z - fj * K1z;
                    float d2m = hmx * hmx + hmy * hmy + hmz * hmz;
                    float Fm = F, Fzm = Fz, Fzzm = Fzz;
                    if (d2m != d2p) Ffuncs(d2m, dz, Fm, Fzm, Fzzm);
                    float cM = cA * cB + sA * sB, sM = sA * cB - cA * sB;
                    accum(cM, sM, hmx, hmy, hmz, Fm, Fzm, Fzzm);
                }
            }
            float cBn = cB * cb - sB * sb;
            sB = sB * cb + cB * sb;
            cB = cBn;
        }
        float cAn = cA * ca - sA * sa;
        sA = sA * ca + cA * sa;
        cA = cAn;
    }

    // S2 (z-only) term
    float az   = AA * dz;
    float erfz = erff(az);
    float egz  = __expf(-az * az);
    float gz   = dz * erfz + egz * INV_A_SQPI;
    float g2z  = TWOA_SQPI * egz;

    // real-space images
    float Er = 0.f, Grx = 0.f, Gry = 0.f, Grz = 0.f;
    float Rxx = 0.f, Ryy = 0.f, Rzz = 0.f, Rxy = 0.f, Rxz = 0.f, Ryz = 0.f;
    #pragma unroll 1
    for (int n0 = -2; n0 <= 2; n0++) {
        #pragma unroll 1
        for (int n1 = -2; n1 <= 2; n1++) {
            float fn0 = (float)n0, fn1 = (float)n1;
            float rx = dx + fn0 * c0x + fn1 * c1x;
            float ry = dy + fn0 * c0y + fn1 * c1y;
            float rz = dz + fn0 * c0z + fn1 * c1z;
            float dd = rx * rx + ry * ry + rz * rz;
            if (dd > 0.f && dd < (81.0f / (AA * AA))) {
                float dr    = sqrtf(dd);
                float ad    = AA * dr;
                float t     = erfcf(ad);
                float e     = __expf(-ad * ad);
                float invd  = __fdividef(1.f, dr);
                float invd2 = invd * invd;
                Er += t * invd;
                float up  = -(TWOA_SQPI * e + t * invd) * invd;
                float upp = TWOA_SQPI * e * (2.f * AA * AA + 2.f * invd2) + 2.f * t * invd * invd2;
                float s1 = up * invd;
                Grx += s1 * rx; Gry += s1 * ry; Grz += s1 * rz;
                float w = (upp - s1) * invd2;
                Rxx += w * rx * rx + s1;
                Ryy += w * ry * ry + s1;
                Rzz += w * rz * rz + s1;
                Rxy += w * rx * ry;
                Rxz += w * rx * rz;
                Ryz += w * ry * rz;
            }
        }
    }

    float PK = KEC * PI_F / area;
    float P3 = 0.5f * KEC;

    float pairE = qq * (PK * (Ek - gz) + P3 * Er);
    float Gx = qq * (PK * Gkx + P3 * Grx);
    float Gy = qq * (PK * Gky + P3 * Gry);
    float Gz = qq * (PK * (Gkz - erfz) + P3 * Grz);

    int o = i * NATOMS + j;
    g_Hc[0][o] = qq * (PK * Kxx + P3 * Rxx);
    g_Hc[1][o] = qq * (PK * Kyy + P3 * Ryy);
    g_Hc[2][o] = qq * (PK * (Kzz - g2z) + P3 * Rzz);
    g_Hc[3][o] = qq * (PK * Kxy + P3 * Rxy);
    g_Hc[4][o] = qq * (PK * Kxz + P3 * Rxz);
    g_Hc[5][o] = qq * (PK * Kyz + P3 * Ryz);

    __shared__ float red[32];
    float se = blockReduce256(pairE, red);
    if (j == 0) atomicAdd(&g_Ec, (double)se);
    float sx = blockReduce256(Gx, red); if (j == 0) g_Gc[i][0] = sx;
    float sy = blockReduce256(Gy, red); if (j == 0) g_Gc[i][1] = sy;
    float sz = blockReduce256(Gz, red); if (j == 0) g_Gc[i][2] = sz;
}

__global__ void k_born(const float* __restrict__ q, const float* __restrict__ off,
                       const float* __restrict__ r0_, const float* __restrict__ n_,
                       const int* __restrict__ ii, const int* __restrict__ jj,
                       const int* __restrict__ mm) {
    int p = blockIdx.x * blockDim.x + threadIdx.x;
    __shared__ float sE[NMOL];
    if (threadIdx.x < NMOL) sE[threadIdx.x] = 0.f;
    __syncthreads();

    int i = ii[p], j = jj[p];
    float rx = g_Rs[j][0] - g_Rs[i][0] + off[p * 3 + 0];
    float ry = g_Rs[j][1] - g_Rs[i][1] + off[p * 3 + 1];
    float rz = g_Rs[j][2] - g_Rs[i][2] + off[p * 3 + 2];
    float d2 = rx * rx + ry * ry + rz * rz;
    float d  = sqrtf(d2);
    float n  = n_[p], r0 = r0_[p];
    float qq = fabsf(q[i] * q[j]);
    float B  = qq * powf(r0, n - 1.f) / n;
    float Hxx = 0.f, Hyy = 0.f, Hzz = 0.f, Hxy = 0.f, Hxz = 0.f, Hyz = 0.f;

    if (d < 6.0f) {
        float dn = powf(d, -n);
        float cn = powf(6.0f, -n);
        float y  = B * (dn - cn);
        atomicAdd(&sE[mm[i]], 0.5f * KEC * y);
        float f   = 0.5f * KEC;
        float yp  = -n * B * dn / d;
        float ypp = n * (n + 1.f) * B * dn / d2;
        float s1  = f * yp / d;
        atomicAdd(&g_Gb[j][0],  s1 * rx);
        atomicAdd(&g_Gb[j][1],  s1 * ry);
        atomicAdd(&g_Gb[j][2],  s1 * rz);
        atomicAdd(&g_Gb[i][0], -s1 * rx);
        atomicAdd(&g_Gb[i][1], -s1 * ry);
        atomicAdd(&g_Gb[i][2], -s1 * rz);
        float w = (f * ypp - s1) / d2;
        Hxx = w * rx * rx + s1; Hyy = w * ry * ry + s1; Hzz = w * rz * rz + s1;
        Hxy = w * rx * ry; Hxz = w * rx * rz; Hyz = w * ry * rz;
    }
    g_Hb[0][p] = Hxx; g_Hb[1][p] = Hyy; g_Hb[2][p] = Hzz;
    g_Hb[3][p] = Hxy; g_Hb[4][p] = Hxz; g_Hb[5][p] = Hyz;

    __syncthreads();
    if (threadIdx.x < NMOL) atomicAdd(&g_Eb[threadIdx.x], (double)sE[threadIdx.x]);
}

__global__ void k_mid(const float* __restrict__ q, const int* __restrict__ idx_m,
                      const int* __restrict__ is_film, float* __restrict__ out) {
    int a = threadIdx.x;
    __shared__ float sff[NMOL * 3];
    __shared__ float red[32];
    if (a < NMOL * 3) sff[a] = 0.f;
    __syncthreads();

    float Fx = -8.f * g_Gc[a][0] - g_Gb[a][0];
    float Fy = -8.f * g_Gc[a][1] - g_Gb[a][1];
    float Fz = -8.f * g_Gc[a][2] - g_Gb[a][2];
    float film = (is_film[a] > 0) ? 1.f : 0.f;
    int m = idx_m[a];
    if (film > 0.f) {
        atomicAdd(&sff[m * 3 + 0], Fx);
        atomicAdd(&sff[m * 3 + 1], Fy);
        atomicAdd(&sff[m * 3 + 2], Fz);
    }
    float sq2 = blockReduce256(q[a] * q[a], red);  // also fences sff atomics

    g_v[a][0] = film * sff[m * 3 + 0];
    g_v[a][1] = film * sff[m * 3 + 1];
    g_v[a][2] = film * sff[m * 3 + 2];

    if (a == 0) {
        float self = -(AA / SQRTPI_F) * KEC * sq2;
        float yc = (float)g_Ec + self;
        out[4] = yc;
        #pragma unroll
        for (int m2 = 0; m2 < NMOL; m2++) {
            float yb = (float)g_Eb[m2];
            out[m2]     = yc + yb;
            out[5 + m2] = yb;
            float fx = sff[m2 * 3 + 0], fy = sff[m2 * 3 + 1], fz = sff[m2 * 3 + 2];
            out[9 + m2] = fx * fx + fy * fy + fz * fz;
        }
    }
}

__global__ void __launch_bounds__(256) k_hvpc() {
    int i = blockIdx.x, j = threadIdx.x;
    float dvx = g_v[i][0] - g_v[j][0];
    float dvy = g_v[i][1] - g_v[j][1];
    float dvz = g_v[i][2] - g_v[j][2];
    int o = i * NATOMS + j;
    float hxx = g_Hc[0][o], hyy = g_Hc[1][o], hzz = g_Hc[2][o];
    float hxy = g_Hc[3][o], hxz = g_Hc[4][o], hyz = g_Hc[5][o];
    float wx = hxx * dvx + hxy * dvy + hxz * dvz;
    float wy = hxy * dvx + hyy * dvy + hyz * dvz;
    float wz = hxz * dvx + hyz * dvy + hzz * dvz;
    __shared__ float red[32];
    float sx = blockReduce256(wx, red); if (j == 0) g_wc[i][0] = sx;
    float sy = blockReduce256(wy, red); if (j == 0) g_wc[i][1] = sy;
    float sz = blockReduce256(wz, red); if (j == 0) g_wc[i][2] = sz;
}

__global__ void k_hvpb(const int* __restrict__ ii, const int* __restrict__ jj) {
    int p = blockIdx.x * blockDim.x + threadIdx.x;
    int i = ii[p], j = jj[p];
    float dvx = g_v[j][0] - g_v[i][0];
    float dvy = g_v[j][1] - g_v[i][1];
    float dvz = g_v[j][2] - g_v[i][2];
    float hxx = g_Hb[0][p], hyy = g_Hb[1][p], hzz = g_Hb[2][p];
    float hxy = g_Hb[3][p], hxz = g_Hb[4][p], hyz = g_Hb[5][p];
    float wx = hxx * dvx + hxy * dvy + hxz * dvz;
    float wy = hxy * dvx + hyy * dvy + hyz * dvz;
    float wz = hxz * dvx + hyz * dvy + hzz * dvz;
    atomicAdd(&g_wb[j][0],  wx);
    atomicAdd(&g_wb[j][1],  wy);
    atomicAdd(&g_wb[j][2],  wz);
    atomicAdd(&g_wb[i][0], -wx);
    atomicAdd(&g_wb[i][1], -wy);
    atomicAdd(&g_wb[i][2], -wz);
}

__global__ void k_fin(const int* __restrict__ idx_m, const int* __restrict__ is_film,
                      float* __restrict__ out) {
    int a = threadIdx.x;
    __shared__ float sf[NMOL * 3];
    if (a < NMOL * 3) sf[a] = 0.f;
    __syncthreads();
    if (is_film[a] > 0) {
        int m = idx_m[a];
        float hx = 8.f * g_wc[a][0] + g_wb[a][0];
        float hy = 8.f * g_wc[a][1] + g_wb[a][1];
        float hz = 8.f * g_wc[a][2] + g_wb[a][2];
        atomicAdd(&sf[m * 3 + 0], hx);
        atomicAdd(&sf[m * 3 + 1], hy);
        atomicAdd(&sf[m * 3 + 2], hz);
    }
    __syncthreads();
    if (a < NMOL * 3) out[13 + a] = -2.f * sf[a];
}

extern "C" void kernel_launch(void* const* d_in, const int* in_sizes, int n_in,
                              void* d_out, int out_size) {
    const float* R      = (const float*)d_in[0];
    const float* shift  = (const float*)d_in[1];
    const float* q      = (const float*)d_in[2];
    const float* off    = (const float*)d_in[3];
    const float* cell   = (const float*)d_in[4];
    const float* recip  = (const float*)d_in[5];
    const float* r0_ij  = (const float*)d_in[6];
    const float* n_ij   = (const float*)d_in[7];
    const int*   idx_i  = (const int*)d_in[8];
    const int*   idx_j  = (const int*)d_in[9];
    const int*   idx_m  = (const int*)d_in[10];
    const int*   isf    = (const int*)d_in[11];
    float* out = (float*)d_out;

    k_prep<<<1, 256>>>(R, shift, idx_m, isf);
    k_coulomb<<<NATOMS, 256>>>(q, cell, recip);
    k_born<<<NPAIRS / 256, 256>>>(q, off, r0_ij, n_ij, idx_i, idx_j, idx_m);
    k_mid<<<1, 256>>>(q, idx_m, isf, out);
    k_hvpc<<<NATOMS, 256>>>();
    k_hvpb<<<NPAIRS / 256, 256>>>(idx_i, idx_j);
    k_fin<<<1, 256>>>(idx_m, isf, out);
}

// round 3
// speedup vs baseline: 1.1506x; 1.1506x over previous
#include <cuda_runtime.h>
#include <cuda_bf16.h>

#define NATOMS 256
#define NMOL   4
#define NPAIRS 8192
#define KEC      14.3996f
#define AA       0.3f
#define PI_F     3.14159265358979323846f
#define SQRTPI_F 1.7724538509055160273f
#define TWOPI_F  6.2831853071795864769f
#define INV2A      (1.0f/(2.0f*AA))
#define TWOA_SQPI  (2.0f*AA/SQRTPI_F)
#define FOURA_SQPI (4.0f*AA/SQRTPI_F)
#define INV_A_SQPI (1.0f/(AA*SQRTPI_F))

__device__ float  g_Rs[NATOMS][3];
__device__ float  g_Hc[6][NATOMS*NATOMS];   // diagonal entries never written -> stay 0
__device__ float  g_Gc[NATOMS][3];
__device__ double g_Ec;
__device__ double g_Eb[NMOL];
__device__ float  g_Gb[NATOMS][3];
__device__ float  g_Hb[6][NPAIRS];
__device__ float  g_v[NATOMS][3];

__device__ __forceinline__ float blockReduce256(float v, float* sh) {
    const unsigned full = 0xffffffffu;
    #pragma unroll
    for (int o = 16; o > 0; o >>= 1) v += __shfl_down_sync(full, v, o);
    int lane = threadIdx.x & 31, w = threadIdx.x >> 5;
    if (lane == 0) sh[w] = v;
    __syncthreads();
    float r = 0.f;
    if (w == 0) {
        r = (lane < (int)(blockDim.x >> 5)) ? sh[lane] : 0.f;
        #pragma unroll
        for (int o = 4; o > 0; o >>= 1) r += __shfl_down_sync(full, r, o);
    }
    __syncthreads();
    return r;
}

// erfc(x)*exp(x*x) for x>=0 (A&S 7.1.26, abs err ~1.5e-7)
__device__ __forceinline__ float erfcx_p(float x) {
    float t = __frcp_rn(fmaf(0.3275911f, x, 1.0f));
    float p = fmaf(t, 1.061405429f, -1.453152027f);
    p = fmaf(t, p, 1.421413741f);
    p = fmaf(t, p, -0.284496736f);
    p = fmaf(t, p, 0.254829592f);
    return t * p;
}

// F(z)=(e1+e2)/d ; F'=e1-e2 ; F''=d(e1+e2)-(4a/sqrt(pi))*g
// e1=exp(dz)erfc(u+az)=g*P(u+az) when u+az>=0, g=exp(-u^2-(az)^2)
__device__ __forceinline__ void Ffuncs(float d2, float z, float az, float azsq,
                                       float& F, float& Fz, float& Fzz) {
    float d  = sqrtf(d2);
    float u  = d * INV2A;
    float dz = d * z;
    float g  = __expf(-fmaf(u, u, azsq));
    float x1 = u + az, x2 = u - az;
    float e1 = g * erfcx_p(fabsf(x1));
    float e2 = g * erfcx_p(fabsf(x2));
    if (x1 < 0.f) e1 = 2.f * __expf(dz)  - e1;
    if (x2 < 0.f) e2 = 2.f * __expf(-dz) - e2;
    float s = e1 + e2;
    F   = __fdividef(s, d);
    Fz  = e1 - e2;
    Fzz = fmaf(d, s, -FOURA_SQPI * g);
}

__global__ void k_prep(const float* __restrict__ R, const float* __restrict__ shift,
                       const int* __restrict__ idx_m, const int* __restrict__ is_film) {
    int a = threadIdx.x;
    int m = idx_m[a];
    float f = (is_film[a] > 0) ? 1.f : 0.f;
    #pragma unroll
    for (int c = 0; c < 3; c++) {
        g_Rs[a][c] = R[a * 3 + c] + f * shift[m * 3 + c];
        g_Gc[a][c] = 0.f;
        g_Gb[a][c] = 0.f;
    }
    if (a == 0) g_Ec = 0.0;
    if (a < NMOL) g_Eb[a] = 0.0;
}

// blocks [0,128): unordered pair rows (b, 255-b); block 128: diagonal energies;
// blocks [129,161): born pairs
__global__ void __launch_bounds__(256) k_main(const float* __restrict__ q,
                                              const float* __restrict__ cell,
                                              const float* __restrict__ recip,
                                              const float* __restrict__ off,
                                              const float* __restrict__ r0_,
                                              const float* __restrict__ n_,
                                              const int* __restrict__ ii,
                                              const int* __restrict__ jj,
                                              const int* __restrict__ mm) {
    __shared__ float red[32];
    int t = threadIdx.x;
    if (blockIdx.x < 129) {
        int b = blockIdx.x;
        bool diag = (b == 128);
        int i = 0, j = 0;
        bool valid;
        if (diag) { i = t; j = t; valid = true; }
        else {
            int n1 = 255 - b;
            if (t < n1)        { i = b;       j = b + 1 + t;            valid = true; }
            else if (t < 255)  { i = 255 - b; j = i + 1 + (t - n1);     valid = true; }
            else               { valid = false; }
        }

        float pairE = 0.f;
        if (valid) {
            float dx = g_Rs[i][0] - g_Rs[j][0];
            float dy = g_Rs[i][1] - g_Rs[j][1];
            float dz = g_Rs[i][2] - g_Rs[j][2];
            float qq = q[i] * q[j];

            float c0x = cell[0], c0y = cell[1], c0z = cell[2];
            float c1x = cell[3], c1y = cell[4], c1z = cell[5];
            float crx = c0y * c1z - c0z * c1y;
            float cry = c0z * c1x - c0x * c1z;
            float crz = c0x * c1y - c0y * c1x;
            float area = sqrtf(crx * crx + cry * cry + crz * crz);
            float K0x = TWOPI_F * recip[0], K0y = TWOPI_F * recip[1], K0z = TWOPI_F * recip[2];
            float K1x = TWOPI_F * recip[3], K1y = TWOPI_F * recip[4], K1z = TWOPI_F * recip[5];

            float az   = AA * dz;
            float azsq = az * az;

            float Ek = 0.f, Gkx = 0.f, Gky = 0.f, Gkz = 0.f;
            float Kxx = 0.f, Kyy = 0.f, Kzz = 0.f, Kxy = 0.f, Kxz = 0.f, Kyz = 0.f;

            float alpha = K0x * dx + K0y * dy + K0z * dz;
            float beta  = K1x * dx + K1y * dy + K1z * dz;
            float sa, ca, sb, cb;
            sincosf(alpha, &sa, &ca);
            sincosf(beta,  &sb, &cb);

            auto accum = [&](float cT, float sT, float hx, float hy, float hz,
                             float F, float Fz, float Fzz) {
                float cF  = cT * F;
                float sF  = sT * F;
                float sFz = sT * Fz;
                Ek  += cF;
                Gkx -= sF * hx;
                Gky -= sF * hy;
                Gkz += cT * Fz - sF * hz;
                Kxx -= cF * hx * hx;
                Kyy -= cF * hy * hy;
                Kxy -= cF * hx * hy;
                Kxz -= cF * hx * hz + sFz * hx;
                Kyz -= cF * hy * hz + sFz * hy;
                Kzz += cT * Fzz - cF * hz * hz - 2.f * sFz * hz;
            };

            float cA = 1.f, sA = 0.f;
            #pragma unroll 1
            for (int k0 = 0; k0 <= 6; k0++) {
                float fk0 = (float)k0;
                float h0x = fk0 * K0x, h0y = fk0 * K0y, h0z = fk0 * K0z;
                float cB, sB;
                int j1s;
                if (k0 == 0) { j1s = 1; cB = cb; sB = sb; }
                else         { j1s = 0; cB = 1.f; sB = 0.f; }
                #pragma unroll 1
                for (int j1 = j1s; j1 <= 6; j1++) {
                    if (j1 == 0) {
                        float d2 = h0x * h0x + h0y * h0y + h0z * h0z;
                        float F, Fz, Fzz; Ffuncs(d2, dz, az, azsq, F, Fz, Fzz);
                        accum(cA, sA, h0x, h0y, h0z, F, Fz, Fzz);
                    } else {
                        float fj = (float)j1;
                        float hpx = h0x + fj * K1x, hpy = h0y + fj * K1y, hpz = h0z + fj * K1z;
                        float d2p = hpx * hpx + hpy * hpy + hpz * hpz;
                        float F, Fz, Fzz; Ffuncs(d2p, dz, az, azsq, F, Fz, Fzz);
                        float cP = cA * cB - sA * sB, sP = sA * cB + cA * sB;
                        accum(cP, sP, hpx, hpy, hpz, F, Fz, Fzz);
                        if (k0 > 0) {
                            float hmx = h0x - fj * K1x, hmy = h0y - fj * K1y, hmz = h0z - fj * K1z;
                            float d2m = hmx * hmx + hmy * hmy + hmz * hmz;
                            float Fm = F, Fzm = Fz, Fzzm = Fzz;
                            if (d2m != d2p) Ffuncs(d2m, dz, az, azsq, Fm, Fzm, Fzzm);
                            float cM = cA * cB + sA * sB, sM = sA * cB - cA * sB;
                            accum(cM, sM, hmx, hmy, hmz, Fm, Fzm, Fzzm);
                        }
                    }
                    float cBn = cB * cb - sB * sb;
                    sB = sB * cb + cB * sb;
                    cB = cBn;
                }
                float cAn = cA * ca - sA * sa;
                sA = sA * ca + cA * sa;
                cA = cAn;
            }

            // S2 (z-only)
            float egz  = __expf(-azsq);
            float erfz = copysignf(1.f - erfcx_p(fabsf(az)) * egz, az);
            float gz   = dz * erfz + egz * INV_A_SQPI;
            float g2z  = TWOA_SQPI * egz;

            // real-space images
            float Er = 0.f, Grx = 0.f, Gry = 0.f, Grz = 0.f;
            float Rxx = 0.f, Ryy = 0.f, Rzz = 0.f, Rxy = 0.f, Rxz = 0.f, Ryz = 0.f;
            #pragma unroll 1
            for (int n0 = -2; n0 <= 2; n0++) {
                #pragma unroll 1
                for (int n1 = -2; n1 <= 2; n1++) {
                    float fn0 = (float)n0, fn1 = (float)n1;
                    float rx = dx + fn0 * c0x + fn1 * c1x;
                    float ry = dy + fn0 * c0y + fn1 * c1y;
                    float rz = dz + fn0 * c0z + fn1 * c1z;
                    float dd = rx * rx + ry * ry + rz * rz;
                    if (dd > 0.f && dd < (81.0f / (AA * AA))) {
                        float dr    = sqrtf(dd);
                        float ad    = AA * dr;
                        float e     = __expf(-ad * ad);
                        float tt    = erfcx_p(ad) * e;
                        float invd  = __fdividef(1.f, dr);
                        float invd2 = invd * invd;
                        Er += tt * invd;
                        float up  = -(TWOA_SQPI * e + tt * invd) * invd;
                        float upp = TWOA_SQPI * e * (2.f * AA * AA + 2.f * invd2) + 2.f * tt * invd * invd2;
                        float s1 = up * invd;
                        Grx += s1 * rx; Gry += s1 * ry; Grz += s1 * rz;
                        float w = (upp - s1) * invd2;
                        Rxx += w * rx * rx + s1;
                        Ryy += w * ry * ry + s1;
                        Rzz += w * rz * rz + s1;
                        Rxy += w * rx * ry;
                        Rxz += w * rx * rz;
                        Ryz += w * ry * rz;
                    }
                }
            }

            float PK = KEC * PI_F / area;
            float P3 = 0.5f * KEC;

            pairE = qq * (PK * (Ek - gz) + P3 * Er);
            if (!diag) {
                pairE *= 2.f;   // ordered-pair double count
                float Gx = qq * (PK * Gkx + P3 * Grx);
                float Gy = qq * (PK * Gky + P3 * Gry);
                float Gz = qq * (PK * (Gkz - erfz) + P3 * Grz);
                atomicAdd(&g_Gc[i][0],  Gx);
                atomicAdd(&g_Gc[i][1],  Gy);
                atomicAdd(&g_Gc[i][2],  Gz);
                atomicAdd(&g_Gc[j][0], -Gx);
                atomicAdd(&g_Gc[j][1], -Gy);
                atomicAdd(&g_Gc[j][2], -Gz);
                float h0 = qq * (PK * Kxx + P3 * Rxx);
                float h1 = qq * (PK * Kyy + P3 * Ryy);
                float h2 = qq * (PK * (Kzz - g2z) + P3 * Rzz);
                float h3 = qq * (PK * Kxy + P3 * Rxy);
                float h4 = qq * (PK * Kxz + P3 * Rxz);
                float h5 = qq * (PK * Kyz + P3 * Ryz);
                int o1 = i * NATOMS + j, o2 = j * NATOMS + i;
                g_Hc[0][o1] = h0; g_Hc[0][o2] = h0;
                g_Hc[1][o1] = h1; g_Hc[1][o2] = h1;
                g_Hc[2][o1] = h2; g_Hc[2][o2] = h2;
                g_Hc[3][o1] = h3; g_Hc[3][o2] = h3;
                g_Hc[4][o1] = h4; g_Hc[4][o2] = h4;
                g_Hc[5][o1] = h5; g_Hc[5][o2] = h5;
            }
        }
        float se = blockReduce256(pairE, red);
        if (t == 0) atomicAdd(&g_Ec, (double)se);
    } else {
        // ---- born pairs ----
        int p = (blockIdx.x - 129) * 256 + t;
        __shared__ float sE[NMOL];
        if (t < NMOL) sE[t] = 0.f;
        __syncthreads();

        int i = ii[p], j = jj[p];
        float rx = g_Rs[j][0] - g_Rs[i][0] + off[p * 3 + 0];
        float ry = g_Rs[j][1] - g_Rs[i][1] + off[p * 3 + 1];
        float rz = g_Rs[j][2] - g_Rs[i][2] + off[p * 3 + 2];
        float d2 = rx * rx + ry * ry + rz * rz;
        float d  = sqrtf(d2);
        float n  = n_[p], r0 = r0_[p];
        float qq = fabsf(q[i] * q[j]);
        float B  = qq * __powf(r0, n - 1.f) * __fdividef(1.f, n);
        float Hxx = 0.f, Hyy = 0.f, Hzz = 0.f, Hxy = 0.f, Hxz = 0.f, Hyz = 0.f;

        if (d < 6.0f) {
            float dn = __powf(d, -n);
            float cn = __powf(6.0f, -n);
            float y  = B * (dn - cn);
            atomicAdd(&sE[mm[i]], 0.5f * KEC * y);
            float f   = 0.5f * KEC;
            float invd  = __fdividef(1.f, d);
            float invd2 = invd * invd;
            float yp  = -n * B * dn * invd;
            float ypp = n * (n + 1.f) * B * dn * invd2;
            float s1  = f * yp * invd;
            atomicAdd(&g_Gb[j][0],  s1 * rx);
            atomicAdd(&g_Gb[j][1],  s1 * ry);
            atomicAdd(&g_Gb[j][2],  s1 * rz);
            atomicAdd(&g_Gb[i][0], -s1 * rx);
            atomicAdd(&g_Gb[i][1], -s1 * ry);
            atomicAdd(&g_Gb[i][2], -s1 * rz);
            float w = (f * ypp - s1) * invd2;
            Hxx = w * rx * rx + s1; Hyy = w * ry * ry + s1; Hzz = w * rz * rz + s1;
            Hxy = w * rx * ry; Hxz = w * rx * rz; Hyz = w * ry * rz;
        }
        g_Hb[0][p] = Hxx; g_Hb[1][p] = Hyy; g_Hb[2][p] = Hzz;
        g_Hb[3][p] = Hxy; g_Hb[4][p] = Hxz; g_Hb[5][p] = Hyz;

        __syncthreads();
        if (t < NMOL) atomicAdd(&g_Eb[t], (double)sE[t]);
    }
}

__global__ void k_mid(const float* __restrict__ q, const int* __restrict__ idx_m,
                      const int* __restrict__ is_film, float* __restrict__ out) {
    int a = threadIdx.x;
    __shared__ float sff[NMOL * 3];
    __shared__ float red[32];
    if (a < NMOL * 3) sff[a] = 0.f;
    if (a >= 32 && a < 44) out[13 + (a - 32)] = 0.f;  // zero fng accumulators
    __syncthreads();

    float Fx = -8.f * g_Gc[a][0] - g_Gb[a][0];
    float Fy = -8.f * g_Gc[a][1] - g_Gb[a][1];
    float Fz = -8.f * g_Gc[a][2] - g_Gb[a][2];
    float film = (is_film[a] > 0) ? 1.f : 0.f;
    int m = idx_m[a];
    if (film > 0.f) {
        atomicAdd(&sff[m * 3 + 0], Fx);
        atomicAdd(&sff[m * 3 + 1], Fy);
        atomicAdd(&sff[m * 3 + 2], Fz);
    }
    float sq2 = blockReduce256(q[a] * q[a], red);  // __syncthreads inside fences sff

    g_v[a][0] = film * sff[m * 3 + 0];
    g_v[a][1] = film * sff[m * 3 + 1];
    g_v[a][2] = film * sff[m * 3 + 2];

    if (a == 0) {
        float self = -(AA / SQRTPI_F) * KEC * sq2;
        float yc = (float)g_Ec + self;
        out[4] = yc;
        #pragma unroll
        for (int m2 = 0; m2 < NMOL; m2++) {
            float yb = (float)g_Eb[m2];
            out[m2]     = yc + yb;
            out[5 + m2] = yb;
            float fx = sff[m2 * 3 + 0], fy = sff[m2 * 3 + 1], fz = sff[m2 * 3 + 2];
            out[9 + m2] = fx * fx + fy * fy + fz * fz;
        }
    }
}

// blocks [0,256): coulomb HVP rows ; blocks [256,288): born HVP pairs
__global__ void __launch_bounds__(256) k_hvp(const int* __restrict__ ii,
                                             const int* __restrict__ jj,
                                             const int* __restrict__ idx_m,
                                             const int* __restrict__ is_film,
                                             float* __restrict__ out) {
    int t = threadIdx.x;
    if (blockIdx.x < 256) {
        int i = blockIdx.x, j = t;
        float dvx = g_v[i][0] - g_v[j][0];
        float dvy = g_v[i][1] - g_v[j][1];
        float dvz = g_v[i][2] - g_v[j][2];
        int o = i * NATOMS + j;
        float hxx = g_Hc[0][o], hyy = g_Hc[1][o], hzz = g_Hc[2][o];
        float hxy = g_Hc[3][o], hxz = g_Hc[4][o], hyz = g_Hc[5][o];
        float wx = hxx * dvx + hxy * dvy + hxz * dvz;
        float wy = hxy * dvx + hyy * dvy + hyz * dvz;
        float wz = hxz * dvx + hyz * dvy + hzz * dvz;
        __shared__ float red[32];
        float sx = blockReduce256(wx, red);
        float sy = blockReduce256(wy, red);
        float sz = blockReduce256(wz, red);
        if (t == 0 && is_film[i] > 0) {
            int m = idx_m[i];
            atomicAdd(&out[13 + m * 3 + 0], -16.f * sx);
            atomicAdd(&out[13 + m * 3 + 1], -16.f * sy);
            atomicAdd(&out[13 + m * 3 + 2], -16.f * sz);
        }
    } else {
        int p = (blockIdx.x - 256) * 256 + t;
        __shared__ float sf[NMOL * 3];
        if (t < NMOL * 3) sf[t] = 0.f;
        __syncthreads();
        int i = ii[p], j = jj[p];
        float dvx = g_v[j][0] - g_v[i][0];
        float dvy = g_v[j][1] - g_v[i][1];
        float dvz = g_v[j][2] - g_v[i][2];
        float hxx = g_Hb[0][p], hyy = g_Hb[1][p], hzz = g_Hb[2][p];
        float hxy = g_Hb[3][p], hxz = g_Hb[4][p], hyz = g_Hb[5][p];
        float wx = hxx * dvx + hxy * dvy + hxz * dvz;
        float wy = hxy * dvx + hyy * dvy + hyz * dvz;
        float wz = hxz * dvx + hyz * dvy + hzz * dvz;
        if (is_film[j] > 0) {
            int mj = idx_m[j];
            atomicAdd(&sf[mj * 3 + 0], -2.f * wx);
            atomicAdd(&sf[mj * 3 + 1], -2.f * wy);
            atomicAdd(&sf[mj * 3 + 2], -2.f * wz);
        }
        if (is_film[i] > 0) {
            int mi = idx_m[i];
            atomicAdd(&sf[mi * 3 + 0],  2.f * wx);
            atomicAdd(&sf[mi * 3 + 1],  2.f * wy);
            atomicAdd(&sf[mi * 3 + 2],  2.f * wz);
        }
        __syncthreads();
        if (t < NMOL * 3) atomicAdd(&out[13 + t], sf[t]);
    }
}

extern "C" void kernel_launch(void* const* d_in, const int* in_sizes, int n_in,
                              void* d_out, int out_size) {
    const float* R      = (const float*)d_in[0];
    const float* shift  = (const float*)d_in[1];
    const float* q      = (const float*)d_in[2];
    const float* off    = (const float*)d_in[3];
    const float* cell   = (const float*)d_in[4];
    const float* recip  = (const float*)d_in[5];
    const float* r0_ij  = (const float*)d_in[6];
    const float* n_ij   = (const float*)d_in[7];
    const int*   idx_i  = (const int*)d_in[8];
    const int*   idx_j  = (const int*)d_in[9];
    const int*   idx_m  = (const int*)d_in[10];
    const int*   isf    = (const int*)d_in[11];
    float* out = (float*)d_out;

    k_prep<<<1, 256>>>(R, shift, idx_m, isf);
    k_main<<<129 + NPAIRS / 256, 256>>>(q, cell, recip, off, r0_ij, n_ij, idx_i, idx_j, idx_m);
    k_mid<<<1, 256>>>(q, idx_m, isf, out);
    k_hvp<<<256 + NPAIRS / 256, 256>>>(idx_i, idx_j, idx_m, isf, out);
}